// round 6
// baseline (speedup 1.0000x reference)
#include <cuda_runtime.h>
#include <cstdint>
#include <cstddef>

// ---------------------------------------------------------------------------
// QAOA diff quantum simulator, N=18 qubits, B=8, 4 layers.
// R6: packed f32x2 butterflies (R5) + 4 CTAs/SM occupancy (EPT=8, 32KB smem).
//
// State: one 16B element per amp pair (bit0): {re0,re1,im0,im1}. Element
// space 17 bits. cb = 6 chunk bits, L = 11 local bits (tid 8 + r 3).
//   Layout A: e = (cb<<11)|L              L0..10=amp1..11, cb=amp12..17
//   Layout B: e = ((L>>5)<<11)|(cb<<5)|(L&31)
//              L0..4=amp1..5, L5..10=amp12..17, cb=amp6..11
// Residencies (r = 3 bits):
//   R0: r=L0..2   R1: r=L3..5   R2: r=L5..7   R3: r=L8..10
// Down pass: R3[pre L8..10] -> R2[pre L5..7, phi, main L5..7]
//   -> R3[main L8..10] -> R1[main L3..4] -> R0[main L0..2 + lane] -> STG.
// Pre (6 bits L5..10) = prev layer's leftover; main = 12 amp bits.
//   A leftover amp12..17 = B's L5..10 ; B leftover amp6..11 = A's L5..10.
// 5 passes: P1(A,init+phi+RX1) P2(B) P3(A) P4(B) P5(A,pre+energy).
// Smem swizzle s^((s>>3)&7): conflict-free for all four patterns.
// ---------------------------------------------------------------------------

namespace {
constexpr int NQ   = 18;
constexpr int QDIM = 1 << NQ;             // 262144 amps
constexpr int EDIM = QDIM / 2;            // 131072 elements
constexpr int NB   = 8;
constexpr int NL   = 4;
constexpr int TPB  = 256;
constexpr int EPT  = 8;                   // elements per thread (r = 3 bits)
constexpr int CHUNKE = TPB * EPT;         // 2048 elements (11 bits)
constexpr int CPB  = EDIM / CHUNKE;       // 64
constexpr int BLOCKS = NB * CPB;          // 512
constexpr size_t SMEM_BYTES = (size_t)CHUNKE * 16; // 32 KB
}

__device__ __align__(256) float4 g_state[(size_t)NB * EDIM]; // 16 MB
__device__ __align__(16) unsigned char g_hp[(size_t)NB * QDIM]; // 2 MB
__device__ float g_partial[BLOCKS];

// --------------------------- packed f32x2 helpers ---------------------------

using u64 = unsigned long long;

__device__ __forceinline__ u64 pk2(float lo, float hi) {
  u64 d; asm("mov.b64 %0, {%1, %2};" : "=l"(d) : "f"(lo), "f"(hi)); return d;
}
__device__ __forceinline__ void upk2(float& lo, float& hi, u64 v) {
  asm("mov.b64 {%0, %1}, %2;" : "=f"(lo), "=f"(hi) : "l"(v));
}
__device__ __forceinline__ u64 mul2(u64 a, u64 b) {
  u64 d; asm("mul.rn.f32x2 %0, %1, %2;" : "=l"(d) : "l"(a), "l"(b)); return d;
}
__device__ __forceinline__ u64 fma2(u64 a, u64 b, u64 c) {
  u64 d; asm("fma.rn.f32x2 %0, %1, %2, %3;" : "=l"(d) : "l"(a), "l"(b), "l"(c));
  return d;
}
__device__ __forceinline__ u64 swp2(u64 v) {
  float lo, hi; upk2(lo, hi, v); return pk2(hi, lo);
}

struct El { u64 re, im; };

// RX butterfly on an element pair (amp bit >= 1)
__device__ __forceinline__ void rot2(El& x, El& y, u64 cc, u64 ss, u64 ns) {
  u64 t1 = mul2(ss, y.im);
  u64 t2 = mul2(ns, y.re);
  u64 t3 = mul2(ss, x.im);
  u64 t4 = mul2(ns, x.re);
  x.re = fma2(cc, x.re, t1);
  x.im = fma2(cc, x.im, t2);
  y.re = fma2(cc, y.re, t3);
  y.im = fma2(cc, y.im, t4);
}
// RX on amp bit 0 (intra-element lane swap)
__device__ __forceinline__ void rot2_lane(El& x, u64 cc, u64 ss, u64 ns) {
  u64 sre = swp2(x.re), sim = swp2(x.im);
  x.re = fma2(cc, x.re, mul2(ss, sim));
  x.im = fma2(cc, x.im, mul2(ns, sre));
}

// butterfly over r-bit P on 8 resident elements
template<int P>
__device__ __forceinline__ void btfE(El* a, u64 cc, u64 ss, u64 ns) {
#pragma unroll
  for (int h = 0; h < EPT / 2; h++) {
    int i0 = ((h >> P) << (P + 1)) | (h & ((1 << P) - 1));
    rot2(a[i0], a[i0 | (1 << P)], cc, ss, ns);
  }
}
__device__ __forceinline__ void btf3(El* a, u64 cc, u64 ss, u64 ns) {
  btfE<0>(a, cc, ss, ns); btfE<1>(a, cc, ss, ns); btfE<2>(a, cc, ss, ns);
}
__device__ __forceinline__ void btf2lo(El* a, u64 cc, u64 ss, u64 ns) {
  btfE<0>(a, cc, ss, ns); btfE<1>(a, cc, ss, ns);
}
__device__ __forceinline__ void btf2hi(El* a, u64 cc, u64 ss, u64 ns) {
  btfE<1>(a, cc, ss, ns); btfE<2>(a, cc, ss, ns);
}

// diagonal phase exp(-i k) per lane
__device__ __forceinline__ void ph2(El& x, const float2* tab, int k0, int k1) {
  float2 p0 = tab[k0], p1 = tab[k1];
  u64 C  = pk2(p0.x, p1.x);
  u64 S  = pk2(p0.y, p1.y);
  u64 nS = pk2(-p0.y, -p1.y);
  u64 t = mul2(S, x.im);
  u64 u = mul2(nS, x.re);
  x.re = fma2(C, x.re, t);
  x.im = fma2(C, x.im, u);
}

// --------------------------- mappings ---------------------------------------

__device__ __forceinline__ int swz(int s) { return s ^ ((s >> 3) & 7); }

template<bool G>
__device__ __forceinline__ int dmap(int cb, int L) {
  if (G)  // B
    return ((L >> 5) << 11) | (cb << 5) | (L & 31);
  else    // A
    return (cb << 11) | L;
}
__device__ __forceinline__ int locR0(int tid, int r) { return (tid << 3) | r; }
__device__ __forceinline__ int locR1(int tid, int r) { return ((tid >> 3) << 6) | (r << 3) | (tid & 7); }
__device__ __forceinline__ int locR2(int tid, int r) { return ((tid >> 5) << 8) | (r << 5) | (tid & 31); }
__device__ __forceinline__ int locR3(int tid, int r) { return (r << 8) | tid; }

// --------------------------- smem element I/O --------------------------------

__device__ __forceinline__ El ld_el(const float4* st4, int e) {
  float4 v = st4[e];
  El x; x.re = pk2(v.x, v.y); x.im = pk2(v.z, v.w); return x;
}
__device__ __forceinline__ void st_el(float4* st4, int e, El x) {
  float4 v; upk2(v.x, v.y, x.re); upk2(v.z, v.w, x.im);
  st4[e] = v;
}
__device__ __forceinline__ void sts_el(float4* sh, int s, El x) {
  float4 v; upk2(v.x, v.y, x.re); upk2(v.z, v.w, x.im);
  sh[s] = v;
}
__device__ __forceinline__ El lds_el(const float4* sh, int s) {
  float4 v = sh[s];
  El x; x.re = pk2(v.x, v.y); x.im = pk2(v.z, v.w); return x;
}

// --------------------------- hp (cut-count) kernel --------------------------

__global__ void hp_kernel(const float* __restrict__ adj) {
  __shared__ int rm[NQ];
  __shared__ int sk[NQ];
  __shared__ int sne;
  const int b = blockIdx.x >> 7;
  const int dbase = (blockIdx.x & 127) << 11;
  const int tid = threadIdx.x;

  if (tid < NQ) {
    int m = 0;
    const float* row = adj + (size_t)b * NQ * NQ + tid * NQ;
    for (int v = tid + 1; v < NQ; v++)
      if (row[v] > 0.5f) m |= 1 << (17 - v);
    rm[tid] = m;
    sk[tid] = __popc(m);
  }
  __syncthreads();
  if (tid == 0) {
    int ne = 0;
    for (int u = 0; u < NQ; u++) ne += sk[u];
    sne = ne;
  }
  __syncthreads();
  const int ne = sne;
  unsigned char* hb = g_hp + (size_t)b * QDIM + dbase;
#pragma unroll
  for (int i = 0; i < 8; i++) {
    int d = dbase + tid + i * 256;
    int cross = 0;
#pragma unroll
    for (int u = 0; u < NQ; u++) {
      int m = rm[u];
      int t = sk[u] - 2 * __popc(d & m);
      cross += ((d >> (17 - u)) & 1) ? -t : t;
    }
    hb[tid + i * 256] = (unsigned char)((ne - cross) >> 1);
  }
}

// --------------------------- P1: init + phi + RX1 (layout A, up) ------------

__global__ void __launch_bounds__(TPB, 4)
pass_init(const float* __restrict__ betas) {
  extern __shared__ float4 sh[];
  __shared__ float2 ph_tab[256];

  const int tid = threadIdx.x;
  const int b = blockIdx.x >> 6, cb = blockIdx.x & 63;

  { float sv, cv; sincosf((float)tid, &sv, &cv); ph_tab[tid] = make_float2(cv, sv); }
  float cm, sm; sincosf(betas[b * NL + 0], &sm, &cm);
  const u64 cc = pk2(cm, cm), ss = pk2(sm, sm), ns = pk2(-sm, -sm);
  __syncthreads();

  const unsigned char* hpb = g_hp + (size_t)b * QDIM;
  float4* st4 = g_state + (size_t)b * EDIM;

  El a[EPT];
  // R0 contiguous: 8 elements -> 16 hp bytes, one uint4
  {
    const float inv = 0.001953125f;  // 1/sqrt(2^18)
    const int e0 = dmap<false>(cb, tid << 3);
    uint4 hv = *reinterpret_cast<const uint4*>(hpb + 2 * (size_t)e0);
    unsigned int w[4] = {hv.x, hv.y, hv.z, hv.w};
#pragma unroll
    for (int r = 0; r < EPT; r++) {
      int k0 = (w[r >> 1] >> ((r & 1) << 4)) & 0xFF;
      int k1 = (w[r >> 1] >> (((r & 1) << 4) + 8)) & 0xFF;
      float2 p0 = ph_tab[k0], p1 = ph_tab[k1];
      a[r].re = pk2(inv * p0.x, inv * p1.x);
      a[r].im = pk2(-inv * p0.y, -inv * p1.y);
    }
  }
  btf3(a, cc, ss, ns);                               // main L0..2
#pragma unroll
  for (int r = 0; r < EPT; r++) rot2_lane(a[r], cc, ss, ns); // amp0
#pragma unroll
  for (int r = 0; r < EPT; r++) sts_el(sh, swz(locR0(tid, r)), a[r]);
  __syncthreads();
#pragma unroll
  for (int r = 0; r < EPT; r++) a[r] = lds_el(sh, swz(locR1(tid, r)));
  btf3(a, cc, ss, ns);                               // main L3..5
#pragma unroll
  for (int r = 0; r < EPT; r++) sts_el(sh, swz(locR1(tid, r)), a[r]); // RMW
  __syncthreads();
#pragma unroll
  for (int r = 0; r < EPT; r++) a[r] = lds_el(sh, swz(locR2(tid, r)));
  btf2hi(a, cc, ss, ns);                             // main L6..7 (L5 done)
#pragma unroll
  for (int r = 0; r < EPT; r++) sts_el(sh, swz(locR2(tid, r)), a[r]); // RMW
  __syncthreads();
#pragma unroll
  for (int r = 0; r < EPT; r++) a[r] = lds_el(sh, swz(locR3(tid, r)));
  btf3(a, cc, ss, ns);                               // main L8..10
#pragma unroll
  for (int r = 0; r < EPT; r++)
    st_el(st4, dmap<false>(cb, locR3(tid, r)), a[r]);
}

// --------------------------- down pass: pre(6) + phi + main(12) -------------

template<bool G>
__global__ void __launch_bounds__(TPB, 4)
pass_down(const float* __restrict__ betas, int pre_layer) {
  extern __shared__ float4 sh[];
  __shared__ float2 ph_tab[256];

  const int tid = threadIdx.x;
  const int b = blockIdx.x >> 6, cb = blockIdx.x & 63;

  { float sv, cv; sincosf((float)tid, &sv, &cv); ph_tab[tid] = make_float2(cv, sv); }
  float cp, sp, cm, sm;
  sincosf(betas[b * NL + pre_layer], &sp, &cp);
  sincosf(betas[b * NL + pre_layer + 1], &sm, &cm);
  const u64 ccp = pk2(cp, cp), ssp = pk2(sp, sp), nsp = pk2(-sp, -sp);
  const u64 ccm = pk2(cm, cm), ssm = pk2(sm, sm), nsm = pk2(-sm, -sm);

  const unsigned char* hpb = g_hp + (size_t)b * QDIM;
  float4* st4 = g_state + (size_t)b * EDIM;

  El a[EPT];
#pragma unroll
  for (int r = 0; r < EPT; r++)
    a[r] = ld_el(st4, dmap<G>(cb, locR3(tid, r)));
  btf3(a, ccp, ssp, nsp);                            // pre L8..10
#pragma unroll
  for (int r = 0; r < EPT; r++) sts_el(sh, swz(locR3(tid, r)), a[r]);
  __syncthreads();                                   // also covers ph_tab
#pragma unroll
  for (int r = 0; r < EPT; r++) a[r] = lds_el(sh, swz(locR2(tid, r)));
  btf3(a, ccp, ssp, nsp);                            // pre L5..7
  // phase: hp bytes of element e = hp[2e], hp[2e+1]
#pragma unroll
  for (int r = 0; r < EPT; r++) {
    int e = dmap<G>(cb, locR2(tid, r));
    unsigned int h = *reinterpret_cast<const unsigned short*>(hpb + 2 * (size_t)e);
    ph2(a[r], ph_tab, h & 0xFF, h >> 8);
  }
  btf3(a, ccm, ssm, nsm);                            // main L5..7
#pragma unroll
  for (int r = 0; r < EPT; r++) sts_el(sh, swz(locR2(tid, r)), a[r]); // RMW
  __syncthreads();
#pragma unroll
  for (int r = 0; r < EPT; r++) a[r] = lds_el(sh, swz(locR3(tid, r)));
  btf3(a, ccm, ssm, nsm);                            // main L8..10
#pragma unroll
  for (int r = 0; r < EPT; r++) sts_el(sh, swz(locR3(tid, r)), a[r]); // RMW
  __syncthreads();
#pragma unroll
  for (int r = 0; r < EPT; r++) a[r] = lds_el(sh, swz(locR1(tid, r)));
  btf2lo(a, ccm, ssm, nsm);                          // main L3..4 (L5 done)
#pragma unroll
  for (int r = 0; r < EPT; r++) sts_el(sh, swz(locR1(tid, r)), a[r]); // RMW
  __syncthreads();
#pragma unroll
  for (int r = 0; r < EPT; r++) a[r] = lds_el(sh, swz(locR0(tid, r)));
  btf3(a, ccm, ssm, nsm);                            // main L0..2
#pragma unroll
  for (int r = 0; r < EPT; r++) rot2_lane(a[r], ccm, ssm, nsm); // amp0
  // R0 contiguous store: 8 consecutive elements per thread
  {
    const int e0 = dmap<G>(cb, tid << 3);
#pragma unroll
    for (int r = 0; r < EPT; r++) st_el(st4, e0 + r, a[r]);
  }
}

// --------------------------- P5: pre RX4 + energy (layout A) ----------------

__global__ void __launch_bounds__(TPB, 4)
pass_energy(const float* __restrict__ betas) {
  extern __shared__ float4 sh[];
  __shared__ float red[TPB / 32];

  const int tid = threadIdx.x;
  const int b = blockIdx.x >> 6, cb = blockIdx.x & 63;

  float cp, sp; sincosf(betas[b * NL + 3], &sp, &cp);
  const u64 ccp = pk2(cp, cp), ssp = pk2(sp, sp), nsp = pk2(-sp, -sp);

  const unsigned char* hpb = g_hp + (size_t)b * QDIM;
  const float4* st4 = g_state + (size_t)b * EDIM;

  El a[EPT];
#pragma unroll
  for (int r = 0; r < EPT; r++)
    a[r] = ld_el(st4, dmap<false>(cb, locR3(tid, r)));
  btf3(a, ccp, ssp, nsp);                            // pre L8..10
#pragma unroll
  for (int r = 0; r < EPT; r++) sts_el(sh, swz(locR3(tid, r)), a[r]);
  __syncthreads();
#pragma unroll
  for (int r = 0; r < EPT; r++) a[r] = lds_el(sh, swz(locR2(tid, r)));
  btf3(a, ccp, ssp, nsp);                            // pre L5..7

  float e = 0.f;
#pragma unroll
  for (int r = 0; r < EPT; r++) {
    int el = dmap<false>(cb, locR2(tid, r));
    unsigned int h = *reinterpret_cast<const unsigned short*>(hpb + 2 * (size_t)el);
    u64 p2 = fma2(a[r].im, a[r].im, mul2(a[r].re, a[r].re));
    float p0, p1; upk2(p0, p1, p2);
    e = fmaf(p0, (float)(h & 0xFF), e);
    e = fmaf(p1, (float)(h >> 8), e);
  }
#pragma unroll
  for (int o = 16; o; o >>= 1) e += __shfl_down_sync(0xffffffffu, e, o);
  if ((tid & 31) == 0) red[tid >> 5] = e;
  __syncthreads();
  if (tid == 0) {
    float t = 0.f;
#pragma unroll
    for (int i = 0; i < TPB / 32; i++) t += red[i];
    g_partial[blockIdx.x] = t;
  }
}

__global__ void k_finish(float* __restrict__ out) {
  int b = threadIdx.x;
  if (b < NB) {
    float t = 0.f;
#pragma unroll
    for (int i = 0; i < CPB; i++) t += g_partial[b * CPB + i];
    out[b] = t;
  }
}

// --------------------------- launch ----------------------------------------

extern "C" void kernel_launch(void* const* d_in, const int* in_sizes, int n_in,
                              void* d_out, int out_size) {
  const float* betas = (const float*)d_in[0];
  const float* adj   = (const float*)d_in[1];
  if (n_in >= 2 && in_sizes[0] != NB * NL) {
    betas = (const float*)d_in[1];
    adj   = (const float*)d_in[0];
  }
  float* out = (float*)d_out;
  (void)out_size;

  cudaFuncSetAttribute(pass_init,        cudaFuncAttributeMaxDynamicSharedMemorySize, (int)SMEM_BYTES);
  cudaFuncSetAttribute(pass_down<true>,  cudaFuncAttributeMaxDynamicSharedMemorySize, (int)SMEM_BYTES);
  cudaFuncSetAttribute(pass_down<false>, cudaFuncAttributeMaxDynamicSharedMemorySize, (int)SMEM_BYTES);
  cudaFuncSetAttribute(pass_energy,      cudaFuncAttributeMaxDynamicSharedMemorySize, (int)SMEM_BYTES);

  hp_kernel<<<NB * 128, 256>>>(adj);
  pass_init<<<BLOCKS, TPB, SMEM_BYTES>>>(betas);           // phi1 + RX1 amp0..11
  pass_down<true ><<<BLOCKS, TPB, SMEM_BYTES>>>(betas, 0); // RX1 12..17, phi, RX2
  pass_down<false><<<BLOCKS, TPB, SMEM_BYTES>>>(betas, 1); // RX2 6..11,  phi, RX3
  pass_down<true ><<<BLOCKS, TPB, SMEM_BYTES>>>(betas, 2); // RX3 12..17, phi, RX4
  pass_energy<<<BLOCKS, TPB, SMEM_BYTES>>>(betas);         // RX4 6..11 + energy
  k_finish<<<1, 32>>>(out);
}

// round 7
// speedup vs baseline: 1.1244x; 1.1244x over previous
#include <cuda_runtime.h>
#include <cstdint>
#include <cstddef>

// ---------------------------------------------------------------------------
// QAOA diff quantum simulator, N=18 qubits, B=8, 4 layers.
// R7: packed f32x2; per down pass only 2 smem exchanges + 1 shuffle-butterfly
//     (leftover bits mapped to local {3, 8..11}); hp fused into P1; final
//     reduce fused into P5 (atomicAdd); PDL overlap between the 5 kernels.
//
// State: 16B element per amp pair (amp bit0): {re0,re1,im0,im1}.
// Element space 17 bits: cb(5) chunk + local(12) = tid(8) + r(4).
// Residencies: S0: local = r<<8|t (r=8..11, lanes=local0..4 -> coalesced LDG)
//              S1: local = (t>>4)<<8 | r<<4 | (t&15)   (r=4..7)
//              S2: local = t<<4|r                       (r=0..3)
// Layouts (e bit k = amp k+1):
//   LAY0 (P1): e = cb<<12 | local                (cb = amp13..17)
//   LAY1 (P2,P4): local0..2->e0..2, local4..7->e3..6, cb->e7..11,
//                 local3->e12, local8..11->e13..16   (pre=amp13..17)
//   LAY2 (P3,P5): local0..2->e0..2, local4..7->e3..6, local3->e7,
//                 local8..11->e8..11, cb->e12..16    (pre=amp8..12)
// Down pass: LDG(S0) + hp prefetch -> pre{r8..11 + shfl local3} -> phi ->
//   main r8..11 -> X->S1: r4..7 -> X->S2: r0..3 + amp0 -> STG.
// Layer coverage: RX1 = P1(13)+P2pre(5); RX2 = P2main(13)+P3pre(5);
//   RX3 = P3main+P4pre; RX4 = P4main+P5pre. phi_t inside P_t. Energy in P5.
// ---------------------------------------------------------------------------

namespace {
constexpr int NQ   = 18;
constexpr int QDIM = 1 << NQ;             // 262144 amps
constexpr int EDIM = QDIM / 2;            // 131072 elements
constexpr int NB   = 8;
constexpr int NL   = 4;
constexpr int TPB  = 256;
constexpr int EPT  = 16;                  // elements per thread (r = 4 bits)
constexpr int CHUNKE = TPB * EPT;         // 4096 elements (12 bits)
constexpr int CPB  = EDIM / CHUNKE;       // 32
constexpr int BLOCKS = NB * CPB;          // 256
constexpr size_t SMEM_BYTES = (size_t)CHUNKE * 16; // 64 KB
}

__device__ __align__(256) float4 g_state[(size_t)NB * EDIM]; // 16 MB
__device__ __align__(16) unsigned char g_hp[(size_t)NB * QDIM]; // 2 MB

// --------------------------- packed f32x2 helpers ---------------------------

using u64 = unsigned long long;

__device__ __forceinline__ u64 pk2(float lo, float hi) {
  u64 d; asm("mov.b64 %0, {%1, %2};" : "=l"(d) : "f"(lo), "f"(hi)); return d;
}
__device__ __forceinline__ void upk2(float& lo, float& hi, u64 v) {
  asm("mov.b64 {%0, %1}, %2;" : "=f"(lo), "=f"(hi) : "l"(v));
}
__device__ __forceinline__ u64 mul2(u64 a, u64 b) {
  u64 d; asm("mul.rn.f32x2 %0, %1, %2;" : "=l"(d) : "l"(a), "l"(b)); return d;
}
__device__ __forceinline__ u64 fma2(u64 a, u64 b, u64 c) {
  u64 d; asm("fma.rn.f32x2 %0, %1, %2, %3;" : "=l"(d) : "l"(a), "l"(b), "l"(c));
  return d;
}
__device__ __forceinline__ u64 swp2(u64 v) {
  float lo, hi; upk2(lo, hi, v); return pk2(hi, lo);
}

struct El { u64 re, im; };

// RX butterfly on an element pair (amp bit >= 1)
__device__ __forceinline__ void rot2(El& x, El& y, u64 cc, u64 ss, u64 ns) {
  u64 t1 = mul2(ss, y.im);
  u64 t2 = mul2(ns, y.re);
  u64 t3 = mul2(ss, x.im);
  u64 t4 = mul2(ns, x.re);
  x.re = fma2(cc, x.re, t1);
  x.im = fma2(cc, x.im, t2);
  y.re = fma2(cc, y.re, t3);
  y.im = fma2(cc, y.im, t4);
}
// RX on amp bit 0 (intra-element lane swap)
__device__ __forceinline__ void rot2_lane(El& x, u64 cc, u64 ss, u64 ns) {
  u64 sre = swp2(x.re), sim = swp2(x.im);
  x.re = fma2(cc, x.re, mul2(ss, sim));
  x.im = fma2(cc, x.im, mul2(ns, sre));
}
// RX on a tid-lane bit via warp shuffle (both roles use same formula)
__device__ __forceinline__ void rot2_shfl(El& x, int lanemask, u64 cc, u64 ss, u64 ns) {
  u64 pre = __shfl_xor_sync(0xffffffffu, x.re, lanemask);
  u64 pim = __shfl_xor_sync(0xffffffffu, x.im, lanemask);
  x.re = fma2(cc, x.re, mul2(ss, pim));
  x.im = fma2(cc, x.im, mul2(ns, pre));
}

// butterfly over r-bit P on 16 resident elements
template<int P>
__device__ __forceinline__ void btfE(El* a, u64 cc, u64 ss, u64 ns) {
#pragma unroll
  for (int h = 0; h < EPT / 2; h++) {
    int i0 = ((h >> P) << (P + 1)) | (h & ((1 << P) - 1));
    rot2(a[i0], a[i0 | (1 << P)], cc, ss, ns);
  }
}
__device__ __forceinline__ void btf4(El* a, u64 cc, u64 ss, u64 ns) {
  btfE<0>(a, cc, ss, ns); btfE<1>(a, cc, ss, ns);
  btfE<2>(a, cc, ss, ns); btfE<3>(a, cc, ss, ns);
}

// --------------------------- mappings ---------------------------------------

__device__ __forceinline__ int swz(int s) { return s ^ ((s >> 4) & 15); }

template<int LAY>
__device__ __forceinline__ int dmap(int cb, int L) {
  if (LAY == 0)
    return (cb << 12) | L;
  else if (LAY == 1)
    return (L & 7) | (((L >> 4) & 15) << 3) | (cb << 7)
         | (((L >> 3) & 1) << 12) | ((L >> 8) << 13);
  else
    return (L & 7) | (((L >> 4) & 15) << 3) | (((L >> 3) & 1) << 7)
         | (((L >> 8) & 15) << 8) | (cb << 12);
}
__device__ __forceinline__ int locS0(int t, int r) { return (r << 8) | t; }
__device__ __forceinline__ int locS1(int t, int r) { return ((t >> 4) << 8) | (r << 4) | (t & 15); }
__device__ __forceinline__ int locS2(int t, int r) { return (t << 4) | r; }

// --------------------------- element I/O -------------------------------------

__device__ __forceinline__ El ld_el(const float4* p, int e) {
  float4 v = p[e];
  El x; x.re = pk2(v.x, v.y); x.im = pk2(v.z, v.w); return x;
}
__device__ __forceinline__ void st_el(float4* p, int e, El x) {
  float4 v; upk2(v.x, v.y, x.re); upk2(v.z, v.w, x.im);
  p[e] = v;
}

// diagonal phase exp(-i k) per lane
__device__ __forceinline__ void ph2(El& x, float2 p0, float2 p1) {
  u64 C  = pk2(p0.x, p1.x);
  u64 S  = pk2(p0.y, p1.y);
  u64 nS = pk2(-p0.y, -p1.y);
  u64 t = mul2(S, x.im);
  u64 u = mul2(nS, x.re);
  x.re = fma2(C, x.re, t);
  x.im = fma2(C, x.im, u);
}

// --------------------------- PDL helpers -------------------------------------

__device__ __forceinline__ void pdl_wait() {
  asm volatile("griddepcontrol.wait;" ::: "memory");
}

// --------------------------- P1: hp + init + phi1 + RX1 ----------------------

__global__ void __launch_bounds__(TPB, 2)
pass_init(const float* __restrict__ betas, const float* __restrict__ adj,
          float* __restrict__ out) {
  extern __shared__ float4 sh[];
  __shared__ float2 ph_tab[256];
  __shared__ int s_rm[NQ];
  __shared__ int s_sk[NQ];

  const int tid = threadIdx.x;
  const int b = blockIdx.x >> 5, cb = blockIdx.x & 31;

  { float sv, cv; sincosf((float)tid, &sv, &cv); ph_tab[tid] = make_float2(cv, sv); }
  if (tid < NQ) {
    int m = 0;
    const float* row = adj + (size_t)b * NQ * NQ + tid * NQ;
    for (int v = tid + 1; v < NQ; v++)
      if (row[v] > 0.5f) m |= 1 << (17 - v);
    s_rm[tid] = m;
    s_sk[tid] = __popc(m);
  }
  if (cb == 0 && tid == 0) out[b] = 0.f;  // zero output for P5 atomics
  float cm, sm; sincosf(betas[b * NL + 0], &sm, &cm);
  const u64 cc = pk2(cm, cm), ss = pk2(sm, sm), ns = pk2(-sm, -sm);
  __syncthreads();

  unsigned char* hpb = g_hp + (size_t)b * QDIM;
  float4* st4 = g_state + (size_t)b * EDIM;

  // ---- hp for this thread's 32 consecutive basis states ----
  const int dbase = (cb << 13) | (tid << 5);
  unsigned int w[8];
  {
    int ne = 0;
#pragma unroll
    for (int u = 0; u < NQ; u++) ne += s_sk[u];
    int cr[32];
#pragma unroll
    for (int j = 0; j < 32; j++) cr[j] = 0;
#pragma unroll
    for (int u = 0; u < NQ; u++) {
      const int m = s_rm[u];
      const int kk = s_sk[u] - 2 * __popc(dbase & m);
      const int mlow = m & 31;
      if (u < 13) {
        const int sgn = (dbase >> (17 - u)) & 1;
#pragma unroll
        for (int j = 0; j < 32; j++) {
          int t2 = kk - 2 * __popc(j & mlow);
          cr[j] += sgn ? -t2 : t2;
        }
      } else {
        const int sb = 17 - u;
#pragma unroll
        for (int j = 0; j < 32; j++) {
          int t2 = kk - 2 * __popc(j & mlow);
          cr[j] += ((j >> sb) & 1) ? -t2 : t2;
        }
      }
    }
#pragma unroll
    for (int q = 0; q < 8; q++) {
      unsigned int p = 0;
#pragma unroll
      for (int e = 0; e < 4; e++)
        p |= (unsigned int)((ne - cr[q * 4 + e]) >> 1) << (e * 8);
      w[q] = p;
    }
    uint4* hdst = reinterpret_cast<uint4*>(hpb + dbase);
    hdst[0] = make_uint4(w[0], w[1], w[2], w[3]);
    hdst[1] = make_uint4(w[4], w[5], w[6], w[7]);
  }

  // ---- init + phi1 (S2 residency: element = dbase/2 + r) ----
  El a[EPT];
  const float inv = 0.001953125f;  // 1/sqrt(2^18)
#pragma unroll
  for (int r = 0; r < EPT; r++) {
    int k0 = (w[r >> 1] >> ((r & 1) << 4)) & 0xFF;
    int k1 = (w[r >> 1] >> (((r & 1) << 4) + 8)) & 0xFF;
    float2 p0 = ph_tab[k0], p1 = ph_tab[k1];
    a[r].re = pk2(inv * p0.x, inv * p1.x);
    a[r].im = pk2(-inv * p0.y, -inv * p1.y);
  }
  // main RX1: S2 r(0..3) + amp0
  btf4(a, cc, ss, ns);
#pragma unroll
  for (int r = 0; r < EPT; r++) rot2_lane(a[r], cc, ss, ns);
#pragma unroll
  for (int r = 0; r < EPT; r++) st_el(sh, swz(locS2(tid, r)), a[r]);
  __syncthreads();
#pragma unroll
  for (int r = 0; r < EPT; r++) a[r] = ld_el(sh, swz(locS1(tid, r)));
  btf4(a, cc, ss, ns);                         // local 4..7
#pragma unroll
  for (int r = 0; r < EPT; r++) st_el(sh, swz(locS1(tid, r)), a[r]); // RMW
  __syncthreads();
#pragma unroll
  for (int r = 0; r < EPT; r++) a[r] = ld_el(sh, swz(locS0(tid, r)));
  btf4(a, cc, ss, ns);                         // local 8..11
#pragma unroll
  for (int r = 0; r < EPT; r++)
    st_el(st4, dmap<0>(cb, locS0(tid, r)), a[r]);   // coalesced
}

// --------------------------- down pass ---------------------------------------

template<int LAY>
__global__ void __launch_bounds__(TPB, 2)
pass_down(const float* __restrict__ betas, int pl) {
  extern __shared__ float4 sh[];
  __shared__ float2 ph_tab[256];

  const int tid = threadIdx.x;
  const int b = blockIdx.x >> 5, cb = blockIdx.x & 31;

  // prologue (independent of upstream results)
  { float sv, cv; sincosf((float)tid, &sv, &cv); ph_tab[tid] = make_float2(cv, sv); }
  float cp, sp, cm, sm;
  sincosf(betas[b * NL + pl], &sp, &cp);
  sincosf(betas[b * NL + pl + 1], &sm, &cm);
  const u64 ccp = pk2(cp, cp), ssp = pk2(sp, sp), nsp = pk2(-sp, -sp);
  const u64 ccm = pk2(cm, cm), ssm = pk2(sm, sm), nsm = pk2(-sm, -sm);

  pdl_wait();  // upstream state+hp now visible

  const unsigned char* hpb = g_hp + (size_t)b * QDIM;
  float4* st4 = g_state + (size_t)b * EDIM;

  El a[EPT];
  unsigned short hw[EPT];
#pragma unroll
  for (int r = 0; r < EPT; r++) {
    int e = dmap<LAY>(cb, locS0(tid, r));
    a[r] = ld_el(st4, e);
    hw[r] = *reinterpret_cast<const unsigned short*>(hpb + 2 * (size_t)e);
  }
  __syncthreads();                       // ph_tab ready (overlaps loads)

  // pre: previous layer leftover = local {8..11} (regs) + local3 (lane bit 3)
  btf4(a, ccp, ssp, nsp);
#pragma unroll
  for (int r = 0; r < EPT; r++) rot2_shfl(a[r], 8, ccp, ssp, nsp);
  // phi
#pragma unroll
  for (int r = 0; r < EPT; r++)
    ph2(a[r], ph_tab[hw[r] & 0xFF], ph_tab[hw[r] >> 8]);
  // main: local 8..11
  btf4(a, ccm, ssm, nsm);
  // X -> S1
#pragma unroll
  for (int r = 0; r < EPT; r++) st_el(sh, swz(locS0(tid, r)), a[r]);
  __syncthreads();
#pragma unroll
  for (int r = 0; r < EPT; r++) a[r] = ld_el(sh, swz(locS1(tid, r)));
  btf4(a, ccm, ssm, nsm);                // local 4..7
  // X -> S2
#pragma unroll
  for (int r = 0; r < EPT; r++) st_el(sh, swz(locS1(tid, r)), a[r]); // RMW
  __syncthreads();
#pragma unroll
  for (int r = 0; r < EPT; r++) a[r] = ld_el(sh, swz(locS2(tid, r)));
  btf4(a, ccm, ssm, nsm);                // local 0..3
#pragma unroll
  for (int r = 0; r < EPT; r++) rot2_lane(a[r], ccm, ssm, nsm); // amp0
#pragma unroll
  for (int r = 0; r < EPT; r++)
    st_el(st4, dmap<LAY>(cb, locS2(tid, r)), a[r]);
}

// --------------------------- P5: pre RX4 + energy -----------------------------

__global__ void __launch_bounds__(TPB, 2)
pass_energy(const float* __restrict__ betas, float* __restrict__ out) {
  __shared__ float red[TPB / 32];

  const int tid = threadIdx.x;
  const int b = blockIdx.x >> 5, cb = blockIdx.x & 31;

  float cp, sp; sincosf(betas[b * NL + 3], &sp, &cp);
  const u64 ccp = pk2(cp, cp), ssp = pk2(sp, sp), nsp = pk2(-sp, -sp);

  pdl_wait();

  const unsigned char* hpb = g_hp + (size_t)b * QDIM;
  const float4* st4 = g_state + (size_t)b * EDIM;

  El a[EPT];
  unsigned short hw[EPT];
#pragma unroll
  for (int r = 0; r < EPT; r++) {
    int e = dmap<2>(cb, locS0(tid, r));
    a[r] = ld_el(st4, e);
    hw[r] = *reinterpret_cast<const unsigned short*>(hpb + 2 * (size_t)e);
  }
  // pre RX4: local {8..11} + local3
  btf4(a, ccp, ssp, nsp);
#pragma unroll
  for (int r = 0; r < EPT; r++) rot2_shfl(a[r], 8, ccp, ssp, nsp);

  float e = 0.f;
#pragma unroll
  for (int r = 0; r < EPT; r++) {
    u64 p2 = fma2(a[r].im, a[r].im, mul2(a[r].re, a[r].re));
    float p0, p1; upk2(p0, p1, p2);
    e = fmaf(p0, (float)(hw[r] & 0xFF), e);
    e = fmaf(p1, (float)(hw[r] >> 8), e);
  }
#pragma unroll
  for (int o = 16; o; o >>= 1) e += __shfl_down_sync(0xffffffffu, e, o);
  if ((tid & 31) == 0) red[tid >> 5] = e;
  __syncthreads();
  if (tid == 0) {
    float t = 0.f;
#pragma unroll
    for (int i = 0; i < TPB / 32; i++) t += red[i];
    atomicAdd(out + b, t);
  }
}

// --------------------------- launch ----------------------------------------

template<typename K, typename... Args>
static void launch_pdl(K kern, Args... args) {
  cudaLaunchConfig_t cfg = {};
  cfg.gridDim = dim3(BLOCKS, 1, 1);
  cfg.blockDim = dim3(TPB, 1, 1);
  cfg.dynamicSmemBytes = SMEM_BYTES;
  cfg.stream = 0;
  cudaLaunchAttribute at[1];
  at[0].id = cudaLaunchAttributeProgrammaticStreamSerialization;
  at[0].val.programmaticStreamSerializationAllowed = 1;
  cfg.attrs = at;
  cfg.numAttrs = 1;
  cudaLaunchKernelEx(&cfg, kern, args...);
}

extern "C" void kernel_launch(void* const* d_in, const int* in_sizes, int n_in,
                              void* d_out, int out_size) {
  const float* betas = (const float*)d_in[0];
  const float* adj   = (const float*)d_in[1];
  if (n_in >= 2 && in_sizes[0] != NB * NL) {
    betas = (const float*)d_in[1];
    adj   = (const float*)d_in[0];
  }
  float* out = (float*)d_out;
  (void)out_size;

  cudaFuncSetAttribute(pass_init,    cudaFuncAttributeMaxDynamicSharedMemorySize, (int)SMEM_BYTES);
  cudaFuncSetAttribute(pass_down<1>, cudaFuncAttributeMaxDynamicSharedMemorySize, (int)SMEM_BYTES);
  cudaFuncSetAttribute(pass_down<2>, cudaFuncAttributeMaxDynamicSharedMemorySize, (int)SMEM_BYTES);
  cudaFuncSetAttribute(pass_energy,  cudaFuncAttributeMaxDynamicSharedMemorySize, (int)SMEM_BYTES);

  pass_init<<<BLOCKS, TPB, SMEM_BYTES>>>(betas, adj, out);  // hp + phi1 + RX1
  launch_pdl(pass_down<1>, betas, 0);   // RX1 amp13..17, phi2, RX2 main
  launch_pdl(pass_down<2>, betas, 1);   // RX2 amp8..12,  phi3, RX3 main
  launch_pdl(pass_down<1>, betas, 2);   // RX3 amp13..17, phi4, RX4 main
  launch_pdl(pass_energy, betas, out);  // RX4 amp8..12 + energy (atomicAdd)
}